// round 10
// baseline (speedup 1.0000x reference)
#include <cuda_runtime.h>
#include <math_constants.h>
#include <cstdint>

#define D_MODEL  1024
#define ALPHA    0.5f
#define WINDOW   64          // 0.5^64 ~ 5e-20: truncation far below 1e-3 rel-err
#define CHUNK    1024        // tokens per EMA chunk
#define ROWS_PER_BLOCK 8     // 8 warps/block, 1 row each
#define BLOCKS_PER_CHUNK (CHUNK / ROWS_PER_BLOCK)   // 128

#define MAX_TOKENS 262144
#define MAX_CHUNKS (MAX_TOKENS / CHUNK)             // 256

// Device globals (no allocation at launch). Zero at module load; the
// observer-reset protocol below restores them to zero before kernel exit,
// so every graph replay starts from the same state.
__device__ float g_scores[MAX_TOKENS];
__device__ int   g_count[MAX_CHUNKS];   // producers done per chunk
__device__ int   g_obs[MAX_CHUNKS];     // consumers done per chunk

__device__ __forceinline__ void atomic_max_float(float* addr, float val)
{
    // Global max is known-positive (~2.9); 0xAA poison is a tiny negative
    // float whose signed-int rep loses to any positive posting.
    if (val >= 0.f)
        atomicMax(reinterpret_cast<int*>(addr), __float_as_int(val));
    else
        atomicMin(reinterpret_cast<unsigned int*>(addr), __float_as_uint(val));
}

// ---------------------------------------------------------------------------
// Single fused kernel.
// Phase 1 (ALL 32768 blocks): R6-winning score structure, untouched.
//   One warp per row, 8 front-batched streaming LDG.128, W in registers.
//   Epilogue: publish chunk-completion counter.
// Phase 2 (last 256 blocks only): adopt chunk i = bid-(grid-256); spin until
//   chunk i and i-1 are produced, compute windowed EMA + block max, atomicMax
//   into out, then run the self-cleaning counter reset.
// ---------------------------------------------------------------------------
__global__ __launch_bounds__(256)
void ema_probe_kernel(const float* __restrict__ x,
                      const float* __restrict__ W,
                      const float* __restrict__ b,
                      float* __restrict__ out,
                      int n)
{
    __shared__ float s[CHUNK + WINDOW];
    __shared__ float wmax[8];

    const int tid  = threadIdx.x;
    const int warp = tid >> 5;
    const int lane = tid & 31;
    const int bid  = blockIdx.x;

    // Initialize output (d_out poisoned to 0xAA; block 0 runs in wave 1,
    // consumers run many microseconds later).
    if (bid == 0 && tid == 0)
        *out = -CUDART_INF_F;

    // ---- Phase 1: score for this block's 8 rows (R6 structure) ----
    const int row = bid * ROWS_PER_BLOCK + warp;
    if (row < n) {
        float4 w[8];
        const float4* W4 = reinterpret_cast<const float4*>(W);
        #pragma unroll
        for (int i = 0; i < 8; i++)
            w[i] = __ldg(&W4[lane + i * 32]);

        const float4* xr = reinterpret_cast<const float4*>(x + (size_t)row * D_MODEL);

        float4 xv[8];
        #pragma unroll
        for (int i = 0; i < 8; i++)                 // 8 front-batched LDG.128
            xv[i] = __ldcs(&xr[lane + i * 32]);

        float acc = 0.f;
        #pragma unroll
        for (int i = 0; i < 8; i++) {
            acc = fmaf(xv[i].x, w[i].x, acc);
            acc = fmaf(xv[i].y, w[i].y, acc);
            acc = fmaf(xv[i].z, w[i].z, acc);
            acc = fmaf(xv[i].w, w[i].w, acc);
        }
        #pragma unroll
        for (int o = 16; o; o >>= 1)
            acc += __shfl_xor_sync(0xffffffffu, acc, o);

        if (lane == 0) {
            g_scores[row] = acc + __ldg(b);
            __threadfence();                        // order store before counter
        }
    }
    __syncthreads();

    const int grid   = gridDim.x;
    const int nchunk = (n + CHUNK - 1) / CHUNK;
    if (tid == 0)
        atomicAdd(&g_count[bid / BLOCKS_PER_CHUNK], 1);

    // ---- Phase 2: EMA role for the last nchunk blocks ----
    const int e = bid - (grid - nchunk);            // chunk index, or <0
    if (e < 0) return;
    const int base = e * CHUNK;

    // Producer target for chunk c (=128 for full chunks)
    auto target = [grid](int c) {
        int hi = (c + 1) * BLOCKS_PER_CHUNK;
        if (hi > grid) hi = grid;
        return hi - c * BLOCKS_PER_CHUNK;
    };

    if (tid == 0) {
        while (atomicAdd(&g_count[e], 0) < target(e))
            __nanosleep(32);
        if (e > 0)
            while (atomicAdd(&g_count[e - 1], 0) < target(e - 1))
                __nanosleep(32);
        __threadfence();                            // acquire producers' stores
    }
    __syncthreads();

    // Load halo + chunk as float4 (272 vectors); base-WINDOW is 4-aligned.
    #pragma unroll
    for (int i = tid; i < (CHUNK + WINDOW) / 4; i += 256) {
        const int g4 = (base - WINDOW) / 4 + i;
        const int g0 = g4 * 4;
        float4 v;
        if (g0 >= 0 && g0 + 3 < n) {
            v = __ldcg(&reinterpret_cast<const float4*>(g_scores)[g4]);
        } else {
            v.x = (g0 + 0 >= 0 && g0 + 0 < n) ? g_scores[g0 + 0] : 0.f;
            v.y = (g0 + 1 >= 0 && g0 + 1 < n) ? g_scores[g0 + 1] : 0.f;
            v.z = (g0 + 2 >= 0 && g0 + 2 < n) ? g_scores[g0 + 2] : 0.f;
            v.w = (g0 + 3 >= 0 && g0 + 3 < n) ? g_scores[g0 + 3] : 0.f;
        }
        *reinterpret_cast<float4*>(&s[i * 4]) = v;
    }
    __syncthreads();

    // Windowed EMA: thread handles 4 consecutive tokens starting at p.
    const int p = tid * 4;
    float eacc = 0.f, wc = ALPHA;
    #pragma unroll
    for (int k = 0; k < WINDOW; k++) {              // 64-tap seed, imm coeffs
        eacc = fmaf(wc, s[WINDOW + p - k], eacc);
        wc *= (1.0f - ALPHA);
    }
    float m = (base + p < n) ? eacc : -CUDART_INF_F;
    #pragma unroll
    for (int j = 1; j < 4; j++) {                   // exact recurrence
        eacc = fmaf(ALPHA, s[WINDOW + p + j], (1.0f - ALPHA) * eacc);
        if (base + p + j < n) m = fmaxf(m, eacc);
    }

    // Block max + global atomic max
    #pragma unroll
    for (int o = 16; o; o >>= 1)
        m = fmaxf(m, __shfl_xor_sync(0xffffffffu, m, o));
    if (lane == 0) wmax[warp] = m;
    __syncthreads();
    if (tid < 8) {
        float r = wmax[tid];
        #pragma unroll
        for (int o = 4; o; o >>= 1)
            r = fmaxf(r, __shfl_xor_sync(0xffu, r, o));
        if (tid == 0)
            atomic_max_float(out, r);
    }

    // ---- Self-cleaning reset (graph-replay safe). Chunk c is observed by
    //      ema blocks c and c+1 (2 observers; 1 for the last chunk). The
    //      FINAL observer — which has necessarily passed its waits and
    //      finished its reads — resets both counters to zero. ----
    __syncthreads();
    if (tid == 0) {
        int t = (e == nchunk - 1) ? 1 : 2;
        if (atomicAdd(&g_obs[e], 1) + 1 == t) {
            atomicExch(&g_count[e], 0);
            atomicExch(&g_obs[e], 0);
        }
        if (e > 0) {
            t = (e - 1 == nchunk - 1) ? 1 : 2;      // always 2 here
            if (atomicAdd(&g_obs[e - 1], 1) + 1 == t) {
                atomicExch(&g_count[e - 1], 0);
                atomicExch(&g_obs[e - 1], 0);
            }
        }
    }
}

// ---------------------------------------------------------------------------
extern "C" void kernel_launch(void* const* d_in, const int* in_sizes, int n_in,
                              void* d_out, int out_size)
{
    const float* x = (const float*)d_in[0];
    const float* W = (const float*)d_in[1];
    const float* b = (const float*)d_in[2];
    float* out     = (float*)d_out;

    const int n = in_sizes[0] / D_MODEL;                 // 262144
    const int grid = (n + ROWS_PER_BLOCK - 1) / ROWS_PER_BLOCK;  // 32768

    ema_probe_kernel<<<grid, 256>>>(x, W, b, out, n);
}

// round 11
// speedup vs baseline: 1.0777x; 1.0777x over previous
#include <cuda_runtime.h>
#include <math_constants.h>
#include <cstdint>

#define D_MODEL  1024
#define ALPHA    0.5f
#define WINDOW   64          // 0.5^64 ~ 5e-20: truncation far below 1e-3 rel-err

// Scratch for per-token scores (1 MB). Device global: no allocation at launch.
#define MAX_TOKENS 262144
__device__ float g_scores[MAX_TOKENS];

// -------------------------------------------------------------------------
// Kernel 1: scores[row] = dot(x[row, :], W) + b   (memory-bound, ~1 GB read)
// FROZEN R6/R9 structure (7.33 TB/s) — do not touch the body. One warp per
// row, single pass, 8 front-batched streaming LDG.128, W in registers,
// PDL trigger at the end.
// -------------------------------------------------------------------------
__global__ __launch_bounds__(256)
void score_kernel(const float* __restrict__ x,
                  const float* __restrict__ W,
                  const float* __restrict__ b,
                  float* __restrict__ out,
                  int n_rows)
{
    const int tid  = threadIdx.x;
    const int warp = tid >> 5;
    const int lane = tid & 31;

    // Initialize output to -inf (d_out is poisoned to 0xAA before timing)
    if (blockIdx.x == 0 && tid == 0)
        *out = -CUDART_INF_F;

    const int row = blockIdx.x * 8 + warp;       // 8 warps/block, 1 row each
    if (row < n_rows) {
        // W into registers: lane covers columns {lane*4 + i*128 .. +3}, i=0..7.
        float4 w[8];
        const float4* W4 = reinterpret_cast<const float4*>(W);
        #pragma unroll
        for (int i = 0; i < 8; i++)
            w[i] = __ldg(&W4[lane + i * 32]);

        const float4* xr = reinterpret_cast<const float4*>(x + (size_t)row * D_MODEL);

        // Front-batch 8 independent streaming LDG.128 (MLP=8/thread)
        float4 xv[8];
        #pragma unroll
        for (int i = 0; i < 8; i++)
            xv[i] = __ldcs(&xr[lane + i * 32]);

        float acc = 0.f;
        #pragma unroll
        for (int i = 0; i < 8; i++) {
            acc = fmaf(xv[i].x, w[i].x, acc);
            acc = fmaf(xv[i].y, w[i].y, acc);
            acc = fmaf(xv[i].z, w[i].z, acc);
            acc = fmaf(xv[i].w, w[i].w, acc);
        }
        #pragma unroll
        for (int o = 16; o; o >>= 1)
            acc += __shfl_xor_sync(0xffffffffu, acc, o);

        if (lane == 0)
            g_scores[row] = acc + __ldg(b);
    }

#if __CUDA_ARCH__ >= 900
    // All threads reach this (no early return above): required for PDL.
    cudaTriggerProgrammaticLaunchCompletion();
#endif
}

// -------------------------------------------------------------------------
// Kernel 2: windowed EMA + global max (PDL secondary), latency-optimized.
// 512 blocks x 4 AUTONOMOUS warps; each warp owns 128 consecutive tokens
// plus its own 64-token halo (no cross-warp coupling -> 2048 independent
// latency chains chip-wide). Seed computed as 4 independent 16-FMA chains
// (exact: window splits with weight 0.5^16 per group), then the exact
// recurrence e = 0.5*s + 0.5*e for 3 more tokens per thread.
// -------------------------------------------------------------------------
__device__ __forceinline__ void atomic_max_float(float* addr, float val)
{
    if (val >= 0.f)
        atomicMax(reinterpret_cast<int*>(addr), __float_as_int(val));
    else
        atomicMin(reinterpret_cast<unsigned int*>(addr), __float_as_uint(val));
}

#define K2_WARP_TOKENS 128
#define K2_WARPS 4

__global__ __launch_bounds__(K2_WARPS * 32)
void ema_max_kernel(float* __restrict__ out, int n)
{
    __shared__ float s[K2_WARPS][K2_WARP_TOKENS + WINDOW];

    const int tid  = threadIdx.x;
    const int warp = tid >> 5;
    const int lane = tid & 31;
    const int gw   = blockIdx.x * K2_WARPS + warp;   // global warp id
    const int base = gw * K2_WARP_TOKENS;

#if __CUDA_ARCH__ >= 900
    // Primary grid's stores to g_scores must be visible before we read.
    cudaGridDependencySynchronize();
#endif
    if (base >= n) return;

    float* sw = s[warp];

    // Load halo + chunk: 192 floats = 48 float4 (base-WINDOW is 4-aligned).
    #pragma unroll
    for (int i = lane; i < (K2_WARP_TOKENS + WINDOW) / 4; i += 32) {
        const int g4 = (base - WINDOW) / 4 + i;
        const int g0 = g4 * 4;
        float4 v;
        if (g0 >= 0 && g0 + 3 < n) {
            v = __ldg(&reinterpret_cast<const float4*>(g_scores)[g4]);
        } else {
            v.x = (g0 + 0 >= 0 && g0 + 0 < n) ? g_scores[g0 + 0] : 0.f;
            v.y = (g0 + 1 >= 0 && g0 + 1 < n) ? g_scores[g0 + 1] : 0.f;
            v.z = (g0 + 2 >= 0 && g0 + 2 < n) ? g_scores[g0 + 2] : 0.f;
            v.w = (g0 + 3 >= 0 && g0 + 3 < n) ? g_scores[g0 + 3] : 0.f;
        }
        *reinterpret_cast<float4*>(&sw[i * 4]) = v;
    }
    __syncwarp();

    // Seed for token base+p: 4 independent 16-tap chains.
    // ema_j = sum_{g=0..3} 0.5^{16g} * sum_{k=0..15} 0.5^{k+1} s_{j-16g-k}
    const int p = lane * 4;
    float a0 = 0.f, a1 = 0.f, a2 = 0.f, a3 = 0.f, wc = ALPHA;
    #pragma unroll
    for (int k = 0; k < 16; k++) {
        a0 = fmaf(wc, sw[WINDOW + p - k],      a0);
        a1 = fmaf(wc, sw[WINDOW + p - 16 - k], a1);
        a2 = fmaf(wc, sw[WINDOW + p - 32 - k], a2);
        a3 = fmaf(wc, sw[WINDOW + p - 48 - k], a3);
        wc *= (1.0f - ALPHA);
    }
    const float c16 = 1.0f / 65536.0f;               // 0.5^16
    float e = fmaf(c16, fmaf(c16, fmaf(c16, a3, a2), a1), a0);
    float m = (base + p < n) ? e : -CUDART_INF_F;

    // Exact recurrence for the next 3 tokens.
    #pragma unroll
    for (int j = 1; j < 4; j++) {
        e = fmaf(ALPHA, sw[WINDOW + p + j], (1.0f - ALPHA) * e);
        if (base + p + j < n) m = fmaxf(m, e);
    }

    // Warp max + one atomic per warp (2048 same-address atomics chip-wide).
    #pragma unroll
    for (int o = 16; o; o >>= 1)
        m = fmaxf(m, __shfl_xor_sync(0xffffffffu, m, o));
    if (lane == 0)
        atomic_max_float(out, m);
}

// -------------------------------------------------------------------------
extern "C" void kernel_launch(void* const* d_in, const int* in_sizes, int n_in,
                              void* d_out, int out_size)
{
    const float* x = (const float*)d_in[0];
    const float* W = (const float*)d_in[1];
    const float* b = (const float*)d_in[2];
    float* out     = (float*)d_out;

    const int n = in_sizes[0] / D_MODEL;    // 262144

    const int grid1 = (n + 7) / 8;                     // 32768 blocks
    score_kernel<<<grid1, 256>>>(x, W, b, out, n);

    // PDL secondary: launch overlaps primary's tail; kernel synchronizes on
    // the primary grid before touching g_scores.
    const int grid2 = (n + K2_WARPS * K2_WARP_TOKENS - 1) / (K2_WARPS * K2_WARP_TOKENS); // 512
    cudaLaunchConfig_t cfg = {};
    cfg.gridDim  = dim3((unsigned)grid2, 1, 1);
    cfg.blockDim = dim3(K2_WARPS * 32, 1, 1);
    cfg.dynamicSmemBytes = 0;
    cfg.stream = 0;
    cudaLaunchAttribute attrs[1];
    attrs[0].id = cudaLaunchAttributeProgrammaticStreamSerialization;
    attrs[0].val.programmaticStreamSerializationAllowed = 1;
    cfg.attrs = attrs;
    cfg.numAttrs = 1;
    cudaError_t err = cudaLaunchKernelEx(&cfg, ema_max_kernel, out, n);
    if (err != cudaSuccess) {
        // Deterministic fallback (attribute support is fixed per driver).
        ema_max_kernel<<<grid2, K2_WARPS * 32>>>(out, n);
    }
}